// round 11
// baseline (speedup 1.0000x reference)
#include <cuda_runtime.h>
#include <cuda_fp16.h>
#include <cstdint>

// Cheb_conv as one batched fp16 GEMM on mma.sync (HMMA), fused conversion:
//   out[b,om,t] = sum_cn W[om,cn] * X[b,cn,t]
//   om=o*24+m (768), cn=c*24+n (768), t=512, b=64.
//   W[om,cn] = M0[c,o](n==m) + M1[c,o]L[n,m] + M2[c,o]L2[n,m]
// R11: no Xt intermediate. CTA=(b, t64) converts its x slice into a RESIDENT
// 96KB fp16 B tile (12 k-chunks), then loops all 6 omt tiles over it,
// streaming A (16KB chunks, single-buffered). 112KB smem -> 2 CTAs/SM.

#define NVERT 24
#define NCH 32
#define NT 512
#define NB 64
#define CN 768
#define OM 768
#define KCH 64          // K chunk (halves) = 128B rows
#define NKCH (CN / KCH) // 12

__device__ float g_L[NVERT * NVERT];
__device__ float g_L2[NVERT * NVERT];
__device__ float g_M[3][NCH][NCH];
__device__ __align__(16) __half g_W[OM * CN];   // row-major [om][cn]

__device__ __forceinline__ uint32_t smem_u32(const void* p) {
    uint32_t a;
    asm("{ .reg .u64 t; cvta.to.shared.u64 t, %1; cvt.u32.u64 %0, t; }" : "=r"(a) : "l"(p));
    return a;
}
#define CP_ASYNC16(dst, src) \
    asm volatile("cp.async.cg.shared.global [%0], [%1], 16;" :: "r"(dst), "l"(src) : "memory")
#define CP_COMMIT() asm volatile("cp.async.commit_group;" ::: "memory")
#define CP_WAIT0()  asm volatile("cp.async.wait_group 0;" ::: "memory")
#define LDSM_X4(r0, r1, r2, r3, a) \
    asm volatile("ldmatrix.sync.aligned.m8n8.x4.shared.b16 {%0,%1,%2,%3}, [%4];" \
                 : "=r"(r0), "=r"(r1), "=r"(r2), "=r"(r3) : "r"(a))
#define MMA16816(c, a, b0, b1) \
    asm volatile("mma.sync.aligned.m16n8k16.row.col.f32.f16.f16.f32 " \
                 "{%0,%1,%2,%3}, {%4,%5,%6,%7}, {%8,%9}, {%0,%1,%2,%3};" \
                 : "+f"((c)[0]), "+f"((c)[1]), "+f"((c)[2]), "+f"((c)[3]) \
                 : "r"((a)[0]), "r"((a)[1]), "r"((a)[2]), "r"((a)[3]), "r"(b0), "r"(b1))

// ---------------- prep1: L, L2, M ----------------
__global__ void cheb_prep1(const float* __restrict__ adj, const float* __restrict__ Theta) {
    __shared__ float dinv[NVERT];
    __shared__ float L[NVERT][NVERT];
    int tid = threadIdx.x;
    if (tid < NVERT) {
        float s = 0.f;
        #pragma unroll
        for (int j = 0; j < NVERT; j++) s += adj[tid * NVERT + j];
        dinv[tid] = (s > 0.f) ? rsqrtf(s) : 0.f;
    }
    __syncthreads();
    for (int idx = tid; idx < NVERT * NVERT; idx += blockDim.x) {
        int i = idx / NVERT, j = idx % NVERT;
        float v = adj[j * NVERT + i] * dinv[i] * dinv[j];
        L[i][j] = v; g_L[idx] = v;
    }
    __syncthreads();
    for (int idx = tid; idx < NVERT * NVERT; idx += blockDim.x) {
        int i = idx / NVERT, j = idx % NVERT;
        float s = 0.f;
        #pragma unroll
        for (int q = 0; q < NVERT; q++) s += L[i][q] * L[q][j];
        g_L2[idx] = s;
    }
    for (int idx = tid; idx < 3 * NCH * NCH; idx += blockDim.x) {
        int blk = idx / (NCH * NCH), r = idx % (NCH * NCH);
        int c = r / NCH, o = r % NCH;
        float v;
        if (blk == 0)      v = Theta[(0 * NCH + c) * NCH + o] - Theta[(2 * NCH + c) * NCH + o];
        else if (blk == 1) v = Theta[(1 * NCH + c) * NCH + o];
        else               v = 2.f * Theta[(2 * NCH + c) * NCH + o];
        g_M[blk][c][o] = v;
    }
}

// ---------------- prepW: W[om][cn] fp16, plain row-major ----------------
__global__ void cheb_prepW() {
    int idx = blockIdx.x * 256 + threadIdx.x;
    int om = idx / CN, cn = idx % CN;
    int o = om / NVERT, m = om % NVERT;
    int c = cn / NVERT, n = cn % NVERT;
    float wv = g_M[1][c][o] * g_L[n * NVERT + m] + g_M[2][c][o] * g_L2[n * NVERT + m];
    if (n == m) wv += g_M[0][c][o];
    g_W[idx] = __float2half_rn(wv);
}

// ---------------- fused GEMM ----------------
// smem layout (per CTA, 112KB):
//   [0 .. 96KB)       B resident: 12 chunks x (64 t-rows x 128B), XOR-swizzled
//   [96KB .. 112KB)   A chunk buffer (128 om-rows x 128B); reused as fp32
//                     staging [64 cn][64 t] during the conversion prologue.
#define SM_B(kc) ((kc) * 8192)
#define SM_A     98304
#define SMEM_TOTAL 114688

__global__ void __launch_bounds__(256, 2) cheb_gemm(const float* __restrict__ x,
                                                    float* __restrict__ out) {
    extern __shared__ __align__(16) unsigned char sm[];
    uint32_t sb = smem_u32(sm);
    int tid = threadIdx.x, lane = tid & 31, warp = tid >> 5;
    int wr = warp & 3, wc = warp >> 2;          // 4(m) x 2(t) warps
    int tt = blockIdx.x, b = blockIdx.z;

    // ---- prologue: convert x[b][:, tt*64..+64) -> resident fp16 B tiles ----
    {
        float* stage = (float*)(sm + SM_A);     // [64 cn][64 t] fp32
        const float* xb = x + (size_t)b * CN * NT + (size_t)tt * KCH;
        for (int kc = 0; kc < NKCH; kc++) {
            const float* src = xb + (size_t)kc * KCH * NT;
            #pragma unroll
            for (int i = 0; i < 4; i++) {
                int idx = tid + 256 * i;        // 0..1023 float4
                int row = idx >> 4, q = idx & 15;
                *(float4*)&stage[row * 64 + q * 4] = *(const float4*)(src + (size_t)row * NT + q * 4);
            }
            __syncthreads();
            #pragma unroll
            for (int it = 0; it < 2; it++) {
                int i = tid + 256 * it;         // 0..511: (t, ch)
                int t = i & 63, ch = i >> 6;    // ch: 8-cn chunk
                __half2 hv[4];
                #pragma unroll
                for (int q = 0; q < 4; q++)
                    hv[q] = __floats2half2_rn(stage[(ch * 8 + 2 * q) * 64 + t],
                                              stage[(ch * 8 + 2 * q + 1) * 64 + t]);
                *(float4*)(sm + SM_B(kc) + t * 128 + ((ch ^ (t & 7)) << 4)) = *(float4*)hv;
            }
            __syncthreads();
        }
    }

    int arow = wr * 32 + (lane & 15);                 // + mi*16
    int ak   = lane >> 4;
    int brow = wc * 32 + (lane & 7) + ((lane >> 4) << 3);   // + njp*16
    int bk   = (lane >> 3) & 1;

    for (int omt = 0; omt < 6; omt++) {
        float acc[2][4][4];
        #pragma unroll
        for (int mi = 0; mi < 2; mi++)
            #pragma unroll
            for (int nj = 0; nj < 4; nj++)
                #pragma unroll
                for (int q = 0; q < 4; q++) acc[mi][nj][q] = 0.f;

        const __half* Ag = g_W + (size_t)(omt * 128) * CN;

        for (int kc = 0; kc < NKCH; kc++) {
            __syncthreads();                    // prior A reads done
            // stream A chunk: 128 om x 64 cn fp16, swizzled
            const __half* as = Ag + kc * KCH;
            #pragma unroll
            for (int i = 0; i < 4; i++) {
                int idx = tid + 256 * i, row = idx >> 3, ch = idx & 7;
                uint32_t d = sb + SM_A + row * 128 + ((ch ^ (row & 7)) << 4);
                CP_ASYNC16(d, as + (size_t)row * CN + ch * 8);
            }
            CP_COMMIT();
            CP_WAIT0();
            __syncthreads();

            uint32_t Ab = sb + SM_A;
            uint32_t Bb = sb + SM_B(kc);
            #pragma unroll
            for (int ks = 0; ks < 4; ks++) {
                uint32_t a[2][4];
                #pragma unroll
                for (int mi = 0; mi < 2; mi++) {
                    int row = arow + mi * 16;
                    int ch = (ks * 2 + ak) ^ (row & 7);
                    LDSM_X4(a[mi][0], a[mi][1], a[mi][2], a[mi][3], Ab + row * 128 + (ch << 4));
                }
                uint32_t bf[4][2];
                #pragma unroll
                for (int njp = 0; njp < 2; njp++) {
                    int row = brow + njp * 16;
                    int ch = (ks * 2 + bk) ^ (row & 7);
                    LDSM_X4(bf[2 * njp][0], bf[2 * njp][1], bf[2 * njp + 1][0], bf[2 * njp + 1][1],
                            Bb + row * 128 + (ch << 4));
                }
                #pragma unroll
                for (int mi = 0; mi < 2; mi++)
                    #pragma unroll
                    for (int nj = 0; nj < 4; nj++)
                        MMA16816(acc[mi][nj], a[mi], bf[nj][0], bf[nj][1]);
            }
        }

        // epilogue for this omt
        int om0 = omt * 128 + wr * 32 + (lane >> 2);
        int t0g = tt * 64 + wc * 32 + (lane & 3) * 2;
        #pragma unroll
        for (int mi = 0; mi < 2; mi++) {
            #pragma unroll
            for (int nj = 0; nj < 4; nj++) {
                float* p0 = out + ((size_t)b * OM + om0 + mi * 16) * NT + t0g + nj * 8;
                *(float2*)p0 = make_float2(acc[mi][nj][0], acc[mi][nj][1]);
                *(float2*)(p0 + 8 * NT) = make_float2(acc[mi][nj][2], acc[mi][nj][3]);
            }
        }
    }
}

extern "C" void kernel_launch(void* const* d_in, const int* in_sizes, int n_in,
                              void* d_out, int out_size) {
    const float* x     = (const float*)d_in[0];   // (64,32,24,512)
    const float* adj   = (const float*)d_in[1];   // (24,24)
    const float* Theta = (const float*)d_in[2];   // (3,32,32)
    float* out = (float*)d_out;                   // (64,32,24,512)

    cudaFuncSetAttribute(cheb_gemm, cudaFuncAttributeMaxDynamicSharedMemorySize, SMEM_TOTAL);

    cheb_prep1<<<1, 128>>>(adj, Theta);
    cheb_prepW<<<(OM * CN) / 256, 256>>>();
    cheb_gemm<<<dim3(NT / KCH, 1, NB), 256, SMEM_TOTAL>>>(x, out);   // 8 tt x 64 b
}